// round 1
// baseline (speedup 1.0000x reference)
#include <cuda_runtime.h>
#include <math.h>

#define N_NODES 38332
#define POI_LEN_ 38333
#define POI_DIM 300
#define CAT_DIM 100
#define FEAT_DIM 403
#define CCH 128
#define NLAYERS 5
#define NEDGES 1200000
#define TOTE (NEDGES + N_NODES)
#define NEG 0.01f
#define GAT_NEG 0.2f

// ---------------- scratch (static __device__, no allocation) ----------------
__device__ float d_feat[N_NODES * FEAT_DIM];
__device__ float d_x [N_NODES * CCH];
__device__ float d_xw[N_NODES * CCH];
__device__ float d_y [N_NODES * CCH];
__device__ int   d_csr_src [TOTE];
__device__ float d_csr_w   [TOTE];
__device__ float d_csr_norm[TOTE];
__device__ int   d_row_ptr[N_NODES + 1];
__device__ int   d_cnt   [N_NODES];
__device__ int   d_cursor[N_NODES];
__device__ float d_dinv[N_NODES];
__device__ float d_al [N_NODES];
__device__ float d_ar [N_NODES];
__device__ float d_xw1[N_NODES];
__device__ float d_xs [N_NODES];
__device__ float d_stat[2 * CCH];
__device__ float d_shift[CCH];
__device__ float d_rstd [CCH];
__device__ float d_hraw[CCH];
__device__ float d_h   [CCH];

__device__ __forceinline__ float leaky01(float v) { return v > 0.f ? v : NEG * v; }
__device__ __forceinline__ float leaky20(float v) { return v > 0.f ? v : GAT_NEG * v; }

// ---------------- CSR build ----------------
__global__ void init_k() {
    int i = blockIdx.x * blockDim.x + threadIdx.x;
    if (i < N_NODES) d_cnt[i] = 1;                 // self-loop pre-counted
    if (i < CCH)     d_hraw[i] = 0.f;
}

__global__ void hist_k(const int* __restrict__ ei) {
    int e = blockIdx.x * blockDim.x + threadIdx.x;
    if (e < NEDGES) atomicAdd(&d_cnt[ei[NEDGES + e]], 1);   // dst row
}

__global__ void scan_k() {
    const int T = 1024;
    const int ITEMS = (N_NODES + T - 1) / T;   // 38
    int tid = threadIdx.x;
    int start = tid * ITEMS;
    int end   = min(start + ITEMS, N_NODES);
    int s = 0;
    for (int i = start; i < end; i++) s += d_cnt[i];
    __shared__ int ps[T];
    ps[tid] = s; __syncthreads();
    for (int off = 1; off < T; off <<= 1) {
        int v = (tid >= off) ? ps[tid - off] : 0;
        __syncthreads();
        ps[tid] += v;
        __syncthreads();
    }
    int incl = ps[tid];
    int run  = incl - s;                        // exclusive prefix
    for (int i = start; i < end; i++) { d_row_ptr[i] = run; run += d_cnt[i]; }
    if (tid == T - 1) d_row_ptr[N_NODES] = incl;
}

__global__ void selfloop_k() {
    int i = blockIdx.x * blockDim.x + threadIdx.x;
    if (i < N_NODES) {
        int p = d_row_ptr[i];
        d_csr_src[p] = i;
        d_csr_w[p]   = 1.0f;
        d_cursor[i]  = p + 1;
    }
}

__global__ void scatter_k(const int* __restrict__ ei, const float* __restrict__ ew) {
    int e = blockIdx.x * blockDim.x + threadIdx.x;
    if (e < NEDGES) {
        int dst = ei[NEDGES + e];
        int p = atomicAdd(&d_cursor[dst], 1);
        d_csr_src[p] = ei[e];
        d_csr_w[p]   = ew[e];
    }
}

__global__ void deg_k() {
    int g = blockIdx.x * blockDim.x + threadIdx.x;
    int node = g >> 5, lane = g & 31;
    if (node >= N_NODES) return;
    int s = d_row_ptr[node], e = d_row_ptr[node + 1];
    float acc = 0.f;
    for (int j = s + lane; j < e; j += 32) acc += d_csr_w[j];
    #pragma unroll
    for (int off = 16; off; off >>= 1) acc += __shfl_down_sync(0xffffffffu, acc, off);
    if (lane == 0) d_dinv[node] = rsqrtf(acc);   // deg >= 1 always (self-loop)
}

__global__ void csnorm_k() {
    int g = blockIdx.x * blockDim.x + threadIdx.x;
    int node = g >> 5, lane = g & 31;
    if (node >= N_NODES) return;
    int s = d_row_ptr[node], e = d_row_ptr[node + 1];
    float dv = d_dinv[node];
    for (int j = s + lane; j < e; j += 32)
        d_csr_norm[j] = d_dinv[d_csr_src[j]] * d_csr_w[j] * dv;
}

// ---------------- feature assembly ----------------
__global__ void feat_k(const int* __restrict__ poi_ids, const int* __restrict__ cat_ids,
                       const float* __restrict__ feat3,
                       const float* __restrict__ poi_emb, const float* __restrict__ cat_emb) {
    int node = blockIdx.x, tid = threadIdx.x;
    int pid = poi_ids[node], cid = cat_ids[node];
    float* f = d_feat + (long)node * FEAT_DIM;
    for (int k = tid; k < POI_DIM; k += 128) f[k] = poi_emb[(long)pid * POI_DIM + k];
    for (int k = tid; k < CAT_DIM; k += 128) f[POI_DIM + k] = cat_emb[cid * CAT_DIM + k];
    if (tid < 3) f[400 + tid] = feat3[node * 3 + tid];
}

// ---------------- GEMM: Y[n,128] = X[n,K] @ W[K,128] ----------------
__global__ void gemm128(const float* __restrict__ X, const float* __restrict__ W,
                        float* __restrict__ Y, int n, int K) {
    __shared__ __align__(16) float xs[64][8];
    __shared__ __align__(16) float ws[8][128];
    int tid = threadIdx.x;
    int tx = tid & 31, ty = tid >> 5;        // tx: col quad, ty: row octet
    int row0 = blockIdx.x * 64;
    float acc[8][4];
    #pragma unroll
    for (int r = 0; r < 8; r++)
        #pragma unroll
        for (int c = 0; c < 4; c++) acc[r][c] = 0.f;

    for (int k0 = 0; k0 < K; k0 += 8) {
        #pragma unroll
        for (int i = 0; i < 2; i++) {
            int e = tid + i * 256;
            int r = e >> 3, kk = e & 7;
            int gr = row0 + r, gk = k0 + kk;
            xs[r][kk] = (gr < n && gk < K) ? X[(long)gr * K + gk] : 0.f;
        }
        #pragma unroll
        for (int i = 0; i < 4; i++) {
            int e = tid + i * 256;
            int kk = e >> 7, c = e & 127;
            int gk = k0 + kk;
            ws[kk][c] = (gk < K) ? W[gk * 128 + c] : 0.f;
        }
        __syncthreads();
        #pragma unroll
        for (int kk = 0; kk < 8; kk++) {
            float4 wv = *(const float4*)&ws[kk][tx * 4];
            #pragma unroll
            for (int r = 0; r < 8; r++) {
                float xv = xs[ty * 8 + r][kk];
                acc[r][0] += xv * wv.x; acc[r][1] += xv * wv.y;
                acc[r][2] += xv * wv.z; acc[r][3] += xv * wv.w;
            }
        }
        __syncthreads();
    }
    #pragma unroll
    for (int r = 0; r < 8; r++) {
        int gr = row0 + ty * 8 + r;
        if (gr < n)
            *(float4*)&Y[(long)gr * 128 + tx * 4] =
                make_float4(acc[r][0], acc[r][1], acc[r][2], acc[r][3]);
    }
}

// ---------------- GCN aggregation (pull, CSR) ----------------
__global__ void gcn_agg(const float* __restrict__ xw, const float* __restrict__ b,
                        float* __restrict__ y, int do_leaky) {
    __shared__ float s_nrm[128];
    __shared__ int   s_src[128];
    int node = blockIdx.x, tid = threadIdx.x;
    int s = d_row_ptr[node], e = d_row_ptr[node + 1];
    float acc = 0.f;
    for (int base = s; base < e; base += 128) {
        int len = min(128, e - base);
        if (tid < len) {
            s_nrm[tid] = d_csr_norm[base + tid];
            s_src[tid] = d_csr_src[base + tid];
        }
        __syncthreads();
        #pragma unroll 4
        for (int q = 0; q < len; q++)
            acc += s_nrm[q] * xw[(long)s_src[q] * CCH + tid];
        __syncthreads();
    }
    acc += b[tid];
    if (do_leaky) acc = leaky01(acc);
    y[(long)node * CCH + tid] = acc;
}

// ---------------- GAT: al/ar ----------------
__global__ void alar_k(const float* __restrict__ xw, const float* __restrict__ asrc,
                       const float* __restrict__ adst) {
    int g = blockIdx.x * blockDim.x + threadIdx.x;
    int node = g >> 5, lane = g & 31;
    if (node >= N_NODES) return;
    float4 v = ((const float4*)(xw + (long)node * CCH))[lane];
    float4 a = ((const float4*)asrc)[lane];
    float4 d = ((const float4*)adst)[lane];
    float dl = v.x * a.x + v.y * a.y + v.z * a.z + v.w * a.w;
    float dr = v.x * d.x + v.y * d.y + v.z * d.z + v.w * d.w;
    #pragma unroll
    for (int off = 16; off; off >>= 1) {
        dl += __shfl_down_sync(0xffffffffu, dl, off);
        dr += __shfl_down_sync(0xffffffffu, dr, off);
    }
    if (lane == 0) { d_al[node] = dl; d_ar[node] = dr; }
}

// ---------------- GAT aggregation: softmax over incoming edges, per node ----------------
__global__ void gat_agg(const float* __restrict__ xw, const float* __restrict__ b,
                        float* __restrict__ y) {
    __shared__ float red[128];
    __shared__ float s_att[128];
    __shared__ int   s_src[128];
    int node = blockIdx.x, tid = threadIdx.x;
    int s = d_row_ptr[node], e = d_row_ptr[node + 1];
    float arn = d_ar[node];

    float m = -1e30f;
    for (int j = s + tid; j < e; j += 128)
        m = fmaxf(m, leaky20(d_al[d_csr_src[j]] + arn));
    red[tid] = m; __syncthreads();
    for (int off = 64; off; off >>= 1) {
        if (tid < off) red[tid] = fmaxf(red[tid], red[tid + off]);
        __syncthreads();
    }
    float bmax = red[0]; __syncthreads();

    float sm = 0.f;
    for (int j = s + tid; j < e; j += 128)
        sm += __expf(leaky20(d_al[d_csr_src[j]] + arn) - bmax);
    red[tid] = sm; __syncthreads();
    for (int off = 64; off; off >>= 1) {
        if (tid < off) red[tid] += red[tid + off];
        __syncthreads();
    }
    float inv_den = 1.f / red[0]; __syncthreads();

    float acc = 0.f;
    for (int base = s; base < e; base += 128) {
        int len = min(128, e - base);
        if (tid < len) {
            int sj = d_csr_src[base + tid];
            s_att[tid] = __expf(leaky20(d_al[sj] + arn) - bmax) * inv_den;
            s_src[tid] = sj;
        }
        __syncthreads();
        #pragma unroll 4
        for (int q = 0; q < len; q++)
            acc += s_att[q] * xw[(long)s_src[q] * CCH + tid];
        __syncthreads();
    }
    y[(long)node * CCH + tid] = acc + b[tid];
}

// ---------------- GraphNorm ----------------
__global__ void zstat_k() { d_stat[threadIdx.x] = 0.f; }   // 256 threads

__global__ void norm_reduce(const float* __restrict__ y) {
    int c = threadIdx.x;
    float ls = 0.f, lq = 0.f;
    for (int n = blockIdx.x; n < N_NODES; n += gridDim.x) {
        float v = y[(long)n * CCH + c];
        ls += v; lq += v * v;
    }
    atomicAdd(&d_stat[c], ls);
    atomicAdd(&d_stat[CCH + c], lq);
}

__global__ void norm_final(const float* __restrict__ alpha) {
    int c = threadIdx.x;
    float m = d_stat[c] * (1.0f / N_NODES);
    float q = d_stat[CCH + c] * (1.0f / N_NODES);
    float a = alpha[c];
    float var = q - (2.f * a - a * a) * m * m;   // E[(y - a*mean)^2]
    d_shift[c] = a * m;
    d_rstd[c]  = rsqrtf(var + 1e-5f);
}

__global__ void norm_apply(const float* __restrict__ y, float* __restrict__ x,
                           const float* __restrict__ gamma, const float* __restrict__ beta) {
    int idx = blockIdx.x * blockDim.x + threadIdx.x;
    if (idx >= N_NODES * CCH) return;
    int c = idx & (CCH - 1);
    float t = gamma[c] * (y[idx] - d_shift[c]) * d_rstd[c] + beta[c];
    x[idx] += leaky01(t);
}

// ---------------- output head ----------------
__global__ void gemv_out(const float* __restrict__ x, const float* __restrict__ Wout) {
    int g = blockIdx.x * blockDim.x + threadIdx.x;
    int node = g >> 5, lane = g & 31;
    if (node >= N_NODES) return;
    float4 v = ((const float4*)(x + (long)node * CCH))[lane];
    float4 w = ((const float4*)Wout)[lane];
    float d = v.x * w.x + v.y * w.y + v.z * w.z + v.w * w.w;
    #pragma unroll
    for (int off = 16; off; off >>= 1) d += __shfl_down_sync(0xffffffffu, d, off);
    if (lane == 0) d_xw1[node] = d;
}

__global__ void scalar_agg(const float* __restrict__ b_out) {
    int g = blockIdx.x * blockDim.x + threadIdx.x;
    int node = g >> 5, lane = g & 31;
    if (node >= N_NODES) return;
    int s = d_row_ptr[node], e = d_row_ptr[node + 1];
    float acc = 0.f;
    for (int j = s + lane; j < e; j += 32)
        acc += d_csr_norm[j] * d_xw1[d_csr_src[j]];
    #pragma unroll
    for (int off = 16; off; off >>= 1) acc += __shfl_down_sync(0xffffffffu, acc, off);
    if (lane == 0) d_xs[node] = leaky01(acc + b_out[0]);
}

__global__ void fc1_partial(const float* __restrict__ W1) {
    int c = threadIdx.x;
    float acc = 0.f;
    for (int n = blockIdx.x; n < N_NODES; n += gridDim.x)
        acc += d_xs[n] * W1[(long)n * CCH + c];
    atomicAdd(&d_hraw[c], acc);
}

__global__ void fc1_final(const float* __restrict__ b1) {
    int c = threadIdx.x;
    float v = d_hraw[c] + b1[c];
    d_h[c] = v > 0.f ? v : 0.f;
}

__global__ void fc2_k(const float* __restrict__ W2, const float* __restrict__ b2,
                      float* __restrict__ out) {
    __shared__ float hs[CCH];
    int tid = threadIdx.x;
    hs[tid] = d_h[tid];
    __syncthreads();
    int p = blockIdx.x * 128 + tid;
    if (p >= POI_LEN_) return;
    float acc = b2[p];
    #pragma unroll 8
    for (int j = 0; j < CCH; j++)
        acc += hs[j] * W2[(long)j * POI_LEN_ + p];
    out[p] = acc > 0.f ? acc : 0.f;
}

// ---------------- launch ----------------
static inline int div_up(int a, int b) { return (a + b - 1) / b; }

extern "C" void kernel_launch(void* const* d_in, const int* in_sizes, int n_in,
                              void* d_out, int out_size) {
    const int*   poi_ids   = (const int*)  d_in[0];
    const int*   cat_ids   = (const int*)  d_in[1];
    const float* feat3     = (const float*)d_in[2];
    const int*   edge_index= (const int*)  d_in[3];
    const float* edge_w    = (const float*)d_in[4];
    const float* poi_emb   = (const float*)d_in[5];
    const float* cat_emb   = (const float*)d_in[6];
    const float* Win       = (const float*)d_in[7];
    const float* b_in      = (const float*)d_in[8];
    const float* gcn_W     = (const float*)d_in[9];
    const float* gcn_b     = (const float*)d_in[10];
    const float* gn_gamma  = (const float*)d_in[11];
    const float* gn_beta   = (const float*)d_in[12];
    const float* gn_alpha  = (const float*)d_in[13];
    const float* gat_W     = (const float*)d_in[14];
    const float* gat_asrc  = (const float*)d_in[15];
    const float* gat_adst  = (const float*)d_in[16];
    const float* gat_b     = (const float*)d_in[17];
    const float* Wout      = (const float*)d_in[18];
    const float* b_out     = (const float*)d_in[19];
    const float* fc_W1     = (const float*)d_in[20];
    const float* fc_b1     = (const float*)d_in[21];
    const float* fc_W2     = (const float*)d_in[22];
    const float* fc_b2     = (const float*)d_in[23];
    float* out = (float*)d_out;

    float *feat_p, *x_p, *xw_p, *y_p;
    cudaGetSymbolAddress((void**)&feat_p, d_feat);
    cudaGetSymbolAddress((void**)&x_p,  d_x);
    cudaGetSymbolAddress((void**)&xw_p, d_xw);
    cudaGetSymbolAddress((void**)&y_p,  d_y);

    const int warpGrid = div_up(N_NODES * 32, 256);
    const int edgeGrid = div_up(NEDGES, 256);
    const int gemmGrid = div_up(N_NODES, 64);

    // CSR build
    init_k<<<div_up(N_NODES, 256), 256>>>();
    hist_k<<<edgeGrid, 256>>>(edge_index);
    scan_k<<<1, 1024>>>();
    selfloop_k<<<div_up(N_NODES, 256), 256>>>();
    scatter_k<<<edgeGrid, 256>>>(edge_index, edge_w);
    deg_k<<<warpGrid, 256>>>();
    csnorm_k<<<warpGrid, 256>>>();

    // features + input conv
    feat_k<<<N_NODES, 128>>>(poi_ids, cat_ids, feat3, poi_emb, cat_emb);
    gemm128<<<gemmGrid, 256>>>(feat_p, Win, xw_p, N_NODES, FEAT_DIM);
    gcn_agg<<<N_NODES, 128>>>(xw_p, b_in, x_p, 1);

    for (int l = 0; l < NLAYERS; l++) {
        // GCN unit half
        gemm128<<<gemmGrid, 256>>>(x_p, gcn_W + l * CCH * CCH, xw_p, N_NODES, CCH);
        gcn_agg<<<N_NODES, 128>>>(xw_p, gcn_b + l * CCH, y_p, 0);
        zstat_k<<<1, 256>>>();
        norm_reduce<<<592, 128>>>(y_p);
        norm_final<<<1, 128>>>(gn_alpha + l * CCH);
        norm_apply<<<div_up(N_NODES * CCH, 256), 256>>>(y_p, x_p, gn_gamma + l * CCH, gn_beta + l * CCH);

        // GAT unit half
        gemm128<<<gemmGrid, 256>>>(x_p, gat_W + l * CCH * CCH, xw_p, N_NODES, CCH);
        alar_k<<<warpGrid, 256>>>(xw_p, gat_asrc + l * CCH, gat_adst + l * CCH);
        gat_agg<<<N_NODES, 128>>>(xw_p, gat_b + l * CCH, y_p);
        zstat_k<<<1, 256>>>();
        norm_reduce<<<592, 128>>>(y_p);
        norm_final<<<1, 128>>>(gn_alpha + l * CCH);
        norm_apply<<<div_up(N_NODES * CCH, 256), 256>>>(y_p, x_p, gn_gamma + l * CCH, gn_beta + l * CCH);
    }

    // output conv + FC head
    gemv_out<<<warpGrid, 256>>>(x_p, Wout);
    scalar_agg<<<warpGrid, 256>>>(b_out);
    fc1_partial<<<592, 128>>>(fc_W1);
    fc1_final<<<1, 128>>>(fc_b1);
    fc2_k<<<div_up(POI_LEN_, 128), 128>>>(fc_W2, fc_b2, out);
}

// round 2
// speedup vs baseline: 1.3525x; 1.3525x over previous
#include <cuda_runtime.h>
#include <mma.h>
#include <math.h>

using namespace nvcuda;

#define N_NODES 38332
#define N_PAD   38400            /* N rounded up to 64 for unguarded wmma stores */
#define POI_LEN_ 38333
#define POI_DIM 300
#define CAT_DIM 100
#define FEAT_DIM 403
#define CCH 128
#define NLAYERS 5
#define NEDGES 1200000
#define TOTE (NEDGES + N_NODES)
#define NEG 0.01f
#define GAT_NEG 0.2f

// ---------------- scratch (static __device__, no allocation) ----------------
__device__ float d_feat[N_NODES * FEAT_DIM];
__device__ float d_x [N_NODES * CCH];
__device__ float d_xw[N_PAD * CCH];      // padded: wmma stores overshoot up to row N_PAD-1
__device__ float d_y [N_NODES * CCH];
__device__ int   d_csr_src [TOTE];
__device__ float d_csr_w   [TOTE];
__device__ float d_csr_norm[TOTE];
__device__ int   d_row_ptr[N_NODES + 1];
__device__ int   d_cnt   [N_NODES];
__device__ int   d_cursor[N_NODES];
__device__ float d_dinv[N_NODES];
__device__ float d_al [N_NODES];
__device__ float d_ar [N_NODES];
__device__ float d_xw1[N_NODES];
__device__ float d_xs [N_NODES];
__device__ float d_stat[2 * CCH];
__device__ float d_shift[CCH];
__device__ float d_rstd [CCH];
__device__ float d_hraw[CCH];
__device__ float d_h   [CCH];

__device__ __forceinline__ float leaky01(float v) { return v > 0.f ? v : NEG * v; }
__device__ __forceinline__ float leaky20(float v) { return v > 0.f ? v : GAT_NEG * v; }

// ---------------- CSR build ----------------
__global__ void init_k() {
    int i = blockIdx.x * blockDim.x + threadIdx.x;
    if (i < N_NODES) d_cnt[i] = 1;                 // self-loop pre-counted
    if (i < CCH)     d_hraw[i] = 0.f;
    if (i < 2 * CCH) d_stat[i] = 0.f;
}

__global__ void hist_k(const int* __restrict__ ei) {
    int e = blockIdx.x * blockDim.x + threadIdx.x;
    if (e < NEDGES) atomicAdd(&d_cnt[ei[NEDGES + e]], 1);   // dst row
}

__global__ void scan_k() {
    const int T = 1024;
    const int ITEMS = (N_NODES + T - 1) / T;   // 38
    int tid = threadIdx.x;
    int start = tid * ITEMS;
    int end   = min(start + ITEMS, N_NODES);
    int s = 0;
    for (int i = start; i < end; i++) s += d_cnt[i];
    __shared__ int ps[T];
    ps[tid] = s; __syncthreads();
    for (int off = 1; off < T; off <<= 1) {
        int v = (tid >= off) ? ps[tid - off] : 0;
        __syncthreads();
        ps[tid] += v;
        __syncthreads();
    }
    int incl = ps[tid];
    int run  = incl - s;                        // exclusive prefix
    for (int i = start; i < end; i++) { d_row_ptr[i] = run; run += d_cnt[i]; }
    if (tid == T - 1) d_row_ptr[N_NODES] = incl;
}

__global__ void selfloop_k() {
    int i = blockIdx.x * blockDim.x + threadIdx.x;
    if (i < N_NODES) {
        int p = d_row_ptr[i];
        d_csr_src[p] = i;
        d_csr_w[p]   = 1.0f;
        d_cursor[i]  = p + 1;
    }
}

__global__ void scatter_k(const int* __restrict__ ei, const float* __restrict__ ew) {
    int e = blockIdx.x * blockDim.x + threadIdx.x;
    if (e < NEDGES) {
        int dst = ei[NEDGES + e];
        int p = atomicAdd(&d_cursor[dst], 1);
        d_csr_src[p] = ei[e];
        d_csr_w[p]   = ew[e];
    }
}

__global__ void deg_k() {
    int g = blockIdx.x * blockDim.x + threadIdx.x;
    int node = g >> 5, lane = g & 31;
    if (node >= N_NODES) return;
    int s = d_row_ptr[node], e = d_row_ptr[node + 1];
    float acc = 0.f;
    for (int j = s + lane; j < e; j += 32) acc += d_csr_w[j];
    #pragma unroll
    for (int off = 16; off; off >>= 1) acc += __shfl_down_sync(0xffffffffu, acc, off);
    if (lane == 0) d_dinv[node] = rsqrtf(acc);   // deg >= 1 always (self-loop)
}

__global__ void csnorm_k() {
    int g = blockIdx.x * blockDim.x + threadIdx.x;
    int node = g >> 5, lane = g & 31;
    if (node >= N_NODES) return;
    int s = d_row_ptr[node], e = d_row_ptr[node + 1];
    float dv = d_dinv[node];
    for (int j = s + lane; j < e; j += 32)
        d_csr_norm[j] = d_dinv[d_csr_src[j]] * d_csr_w[j] * dv;
}

// ---------------- feature assembly ----------------
__global__ void feat_k(const int* __restrict__ poi_ids, const int* __restrict__ cat_ids,
                       const float* __restrict__ feat3,
                       const float* __restrict__ poi_emb, const float* __restrict__ cat_emb) {
    int node = blockIdx.x, tid = threadIdx.x;
    int pid = poi_ids[node], cid = cat_ids[node];
    float* f = d_feat + (long)node * FEAT_DIM;
    for (int k = tid; k < POI_DIM; k += 128) f[k] = poi_emb[(long)pid * POI_DIM + k];
    for (int k = tid; k < CAT_DIM; k += 128) f[POI_DIM + k] = cat_emb[cid * CAT_DIM + k];
    if (tid < 3) f[400 + tid] = feat3[node * 3 + tid];
}

// ---------------- GEMM (tf32 tensor cores): Y[n,128] = X[n,K] @ W[K,128] ----------------
// Block tile 64x128, 8 warps each 32x32, m16n16k8 tf32 fragments.
// Y must be padded to a multiple of 64 rows (d_xw is).
#define GM 64
#define GN 128
#define GK 16

__global__ __launch_bounds__(256) void gemm_tf32(const float* __restrict__ X,
                                                 const float* __restrict__ W,
                                                 float* __restrict__ Y, int n, int K) {
    __shared__ __align__(16) float Xs[GM][GK];
    __shared__ __align__(16) float Ws[GK][GN];
    int tid = threadIdx.x;
    int warp = tid >> 5;
    int wm = warp & 1;       // row group (32 rows)
    int wn = warp >> 1;      // col group (32 cols)
    int row0 = blockIdx.x * GM;

    wmma::fragment<wmma::accumulator, 16, 16, 8, float> c[2][2];
    #pragma unroll
    for (int i = 0; i < 2; i++)
        #pragma unroll
        for (int j = 0; j < 2; j++) wmma::fill_fragment(c[i][j], 0.f);

    for (int k0 = 0; k0 < K; k0 += GK) {
        #pragma unroll
        for (int i = 0; i < 4; i++) {            // Xs: 1024 floats, scalar (K may be odd)
            int e = tid + i * 256;
            int r = e >> 4, kk = e & 15;
            int gr = row0 + r, gk = k0 + kk;
            Xs[r][kk] = (gr < n && gk < K) ? X[(long)gr * K + gk] : 0.f;
        }
        #pragma unroll
        for (int i = 0; i < 2; i++) {            // Ws: 2048 floats, float4
            int e = tid + i * 256;               // float4 slot in [0,512)
            int kk = e >> 5, c4 = e & 31;
            int gk = k0 + kk;
            float4 v = (gk < K) ? ((const float4*)(W + (long)gk * GN))[c4]
                                : make_float4(0.f, 0.f, 0.f, 0.f);
            ((float4*)&Ws[kk][0])[c4] = v;
        }
        __syncthreads();
        #pragma unroll
        for (int ks = 0; ks < 2; ks++) {
            wmma::fragment<wmma::matrix_a, 16, 16, 8, wmma::precision::tf32, wmma::row_major> a[2];
            wmma::fragment<wmma::matrix_b, 16, 16, 8, wmma::precision::tf32, wmma::row_major> bf[2];
            #pragma unroll
            for (int i = 0; i < 2; i++) {
                wmma::load_matrix_sync(a[i], &Xs[wm * 32 + i * 16][ks * 8], GK);
                #pragma unroll
                for (int t = 0; t < a[i].num_elements; t++)
                    a[i].x[t] = wmma::__float_to_tf32(a[i].x[t]);
            }
            #pragma unroll
            for (int j = 0; j < 2; j++) {
                wmma::load_matrix_sync(bf[j], &Ws[ks * 8][wn * 32 + j * 16], GN);
                #pragma unroll
                for (int t = 0; t < bf[j].num_elements; t++)
                    bf[j].x[t] = wmma::__float_to_tf32(bf[j].x[t]);
            }
            #pragma unroll
            for (int i = 0; i < 2; i++)
                #pragma unroll
                for (int j = 0; j < 2; j++)
                    wmma::mma_sync(c[i][j], a[i], bf[j], c[i][j]);
        }
        __syncthreads();
    }
    #pragma unroll
    for (int i = 0; i < 2; i++)
        #pragma unroll
        for (int j = 0; j < 2; j++)
            wmma::store_matrix_sync(Y + (long)(row0 + wm * 32 + i * 16) * GN + wn * 32 + j * 16,
                                    c[i][j], GN, wmma::mem_row_major);
}

// ---------------- GCN aggregation: warp per node, float4 channels ----------------
__global__ __launch_bounds__(256) void gcn_agg_v2(const float* __restrict__ xw,
                                                  const float* __restrict__ b,
                                                  float* __restrict__ y, int do_leaky) {
    int node = (blockIdx.x * blockDim.x + threadIdx.x) >> 5;
    int lane = threadIdx.x & 31;
    if (node >= N_NODES) return;
    int s = d_row_ptr[node], e = d_row_ptr[node + 1];
    float4 acc = make_float4(0.f, 0.f, 0.f, 0.f);
    for (int base = s; base < e; base += 32) {
        int j = base + lane;
        int srcL = 0; float nrmL = 0.f;
        if (j < e) { srcL = d_csr_src[j]; nrmL = d_csr_norm[j]; }
        int cnt = min(32, e - base);
        for (int q = 0; q < cnt; q++) {
            int   sq = __shfl_sync(0xffffffffu, srcL, q);
            float nq = __shfl_sync(0xffffffffu, nrmL, q);
            float4 v = ((const float4*)(xw + (long)sq * CCH))[lane];
            acc.x += nq * v.x; acc.y += nq * v.y;
            acc.z += nq * v.z; acc.w += nq * v.w;
        }
    }
    float4 bb = ((const float4*)b)[lane];
    acc.x += bb.x; acc.y += bb.y; acc.z += bb.z; acc.w += bb.w;
    if (do_leaky) {
        acc.x = leaky01(acc.x); acc.y = leaky01(acc.y);
        acc.z = leaky01(acc.z); acc.w = leaky01(acc.w);
    }
    ((float4*)(y + (long)node * CCH))[lane] = acc;
}

// ---------------- GAT: al/ar ----------------
__global__ void alar_k(const float* __restrict__ xw, const float* __restrict__ asrc,
                       const float* __restrict__ adst) {
    int g = blockIdx.x * blockDim.x + threadIdx.x;
    int node = g >> 5, lane = g & 31;
    if (node >= N_NODES) return;
    float4 v = ((const float4*)(xw + (long)node * CCH))[lane];
    float4 a = ((const float4*)asrc)[lane];
    float4 d = ((const float4*)adst)[lane];
    float dl = v.x * a.x + v.y * a.y + v.z * a.z + v.w * a.w;
    float dr = v.x * d.x + v.y * d.y + v.z * d.z + v.w * d.w;
    #pragma unroll
    for (int off = 16; off; off >>= 1) {
        dl += __shfl_down_sync(0xffffffffu, dl, off);
        dr += __shfl_down_sync(0xffffffffu, dr, off);
    }
    if (lane == 0) { d_al[node] = dl; d_ar[node] = dr; }
}

// ---------------- GAT aggregation: warp per node ----------------
__global__ __launch_bounds__(256) void gat_agg_v2(const float* __restrict__ xw,
                                                  const float* __restrict__ b,
                                                  float* __restrict__ y) {
    int node = (blockIdx.x * blockDim.x + threadIdx.x) >> 5;
    int lane = threadIdx.x & 31;
    if (node >= N_NODES) return;
    int s = d_row_ptr[node], e = d_row_ptr[node + 1];
    float arn = d_ar[node];

    float m = -1e30f;
    for (int j = s + lane; j < e; j += 32)
        m = fmaxf(m, leaky20(d_al[d_csr_src[j]] + arn));
    #pragma unroll
    for (int off = 16; off; off >>= 1) m = fmaxf(m, __shfl_xor_sync(0xffffffffu, m, off));

    float sm = 0.f;
    for (int j = s + lane; j < e; j += 32)
        sm += __expf(leaky20(d_al[d_csr_src[j]] + arn) - m);
    #pragma unroll
    for (int off = 16; off; off >>= 1) sm += __shfl_xor_sync(0xffffffffu, sm, off);
    float inv = 1.f / sm;

    float4 acc = make_float4(0.f, 0.f, 0.f, 0.f);
    for (int base = s; base < e; base += 32) {
        int j = base + lane;
        int srcL = 0; float attL = 0.f;
        if (j < e) {
            srcL = d_csr_src[j];
            attL = __expf(leaky20(d_al[srcL] + arn) - m) * inv;
        }
        int cnt = min(32, e - base);
        for (int q = 0; q < cnt; q++) {
            int   sq = __shfl_sync(0xffffffffu, srcL, q);
            float aq = __shfl_sync(0xffffffffu, attL, q);
            float4 v = ((const float4*)(xw + (long)sq * CCH))[lane];
            acc.x += aq * v.x; acc.y += aq * v.y;
            acc.z += aq * v.z; acc.w += aq * v.w;
        }
    }
    float4 bb = ((const float4*)b)[lane];
    ((float4*)(y + (long)node * CCH))[lane] =
        make_float4(acc.x + bb.x, acc.y + bb.y, acc.z + bb.z, acc.w + bb.w);
}

// ---------------- GraphNorm ----------------
__global__ void norm_reduce(const float* __restrict__ y) {
    int c = threadIdx.x;
    float ls = 0.f, lq = 0.f;
    for (int n = blockIdx.x; n < N_NODES; n += gridDim.x) {
        float v = y[(long)n * CCH + c];
        ls += v; lq += v * v;
    }
    atomicAdd(&d_stat[c], ls);
    atomicAdd(&d_stat[CCH + c], lq);
}

__global__ void norm_final(const float* __restrict__ alpha) {
    int c = threadIdx.x;
    float m = d_stat[c] * (1.0f / N_NODES);
    float q = d_stat[CCH + c] * (1.0f / N_NODES);
    float a = alpha[c];
    float var = q - (2.f * a - a * a) * m * m;   // E[(y - a*mean)^2]
    d_shift[c] = a * m;
    d_rstd[c]  = rsqrtf(var + 1e-5f);
    d_stat[c] = 0.f;            // reset for next layer
    d_stat[CCH + c] = 0.f;
}

__global__ void norm_apply(const float* __restrict__ y, float* __restrict__ x,
                           const float* __restrict__ gamma, const float* __restrict__ beta) {
    int idx = blockIdx.x * blockDim.x + threadIdx.x;
    if (idx >= N_NODES * CCH) return;
    int c = idx & (CCH - 1);
    float t = gamma[c] * (y[idx] - d_shift[c]) * d_rstd[c] + beta[c];
    x[idx] += leaky01(t);
}

// ---------------- output head ----------------
__global__ void gemv_out(const float* __restrict__ x, const float* __restrict__ Wout) {
    int g = blockIdx.x * blockDim.x + threadIdx.x;
    int node = g >> 5, lane = g & 31;
    if (node >= N_NODES) return;
    float4 v = ((const float4*)(x + (long)node * CCH))[lane];
    float4 w = ((const float4*)Wout)[lane];
    float d = v.x * w.x + v.y * w.y + v.z * w.z + v.w * w.w;
    #pragma unroll
    for (int off = 16; off; off >>= 1) d += __shfl_down_sync(0xffffffffu, d, off);
    if (lane == 0) d_xw1[node] = d;
}

__global__ void scalar_agg(const float* __restrict__ b_out) {
    int g = blockIdx.x * blockDim.x + threadIdx.x;
    int node = g >> 5, lane = g & 31;
    if (node >= N_NODES) return;
    int s = d_row_ptr[node], e = d_row_ptr[node + 1];
    float acc = 0.f;
    for (int j = s + lane; j < e; j += 32)
        acc += d_csr_norm[j] * d_xw1[d_csr_src[j]];
    #pragma unroll
    for (int off = 16; off; off >>= 1) acc += __shfl_down_sync(0xffffffffu, acc, off);
    if (lane == 0) d_xs[node] = leaky01(acc + b_out[0]);
}

__global__ void fc1_partial(const float* __restrict__ W1) {
    int c = threadIdx.x;
    float acc = 0.f;
    for (int n = blockIdx.x; n < N_NODES; n += gridDim.x)
        acc += d_xs[n] * W1[(long)n * CCH + c];
    atomicAdd(&d_hraw[c], acc);
}

__global__ void fc1_final(const float* __restrict__ b1) {
    int c = threadIdx.x;
    float v = d_hraw[c] + b1[c];
    d_h[c] = v > 0.f ? v : 0.f;
}

__global__ void fc2_k(const float* __restrict__ W2, const float* __restrict__ b2,
                      float* __restrict__ out) {
    __shared__ float hs[CCH];
    int tid = threadIdx.x;
    hs[tid] = d_h[tid];
    __syncthreads();
    int p = blockIdx.x * 128 + tid;
    if (p >= POI_LEN_) return;
    float acc = b2[p];
    #pragma unroll 8
    for (int j = 0; j < CCH; j++)
        acc += hs[j] * W2[(long)j * POI_LEN_ + p];
    out[p] = acc > 0.f ? acc : 0.f;
}

// ---------------- launch ----------------
static inline int div_up(int a, int b) { return (a + b - 1) / b; }

extern "C" void kernel_launch(void* const* d_in, const int* in_sizes, int n_in,
                              void* d_out, int out_size) {
    const int*   poi_ids   = (const int*)  d_in[0];
    const int*   cat_ids   = (const int*)  d_in[1];
    const float* feat3     = (const float*)d_in[2];
    const int*   edge_index= (const int*)  d_in[3];
    const float* edge_w    = (const float*)d_in[4];
    const float* poi_emb   = (const float*)d_in[5];
    const float* cat_emb   = (const float*)d_in[6];
    const float* Win       = (const float*)d_in[7];
    const float* b_in      = (const float*)d_in[8];
    const float* gcn_W     = (const float*)d_in[9];
    const float* gcn_b     = (const float*)d_in[10];
    const float* gn_gamma  = (const float*)d_in[11];
    const float* gn_beta   = (const float*)d_in[12];
    const float* gn_alpha  = (const float*)d_in[13];
    const float* gat_W     = (const float*)d_in[14];
    const float* gat_asrc  = (const float*)d_in[15];
    const float* gat_adst  = (const float*)d_in[16];
    const float* gat_b     = (const float*)d_in[17];
    const float* Wout      = (const float*)d_in[18];
    const float* b_out     = (const float*)d_in[19];
    const float* fc_W1     = (const float*)d_in[20];
    const float* fc_b1     = (const float*)d_in[21];
    const float* fc_W2     = (const float*)d_in[22];
    const float* fc_b2     = (const float*)d_in[23];
    float* out = (float*)d_out;

    float *feat_p, *x_p, *xw_p, *y_p;
    cudaGetSymbolAddress((void**)&feat_p, d_feat);
    cudaGetSymbolAddress((void**)&x_p,  d_x);
    cudaGetSymbolAddress((void**)&xw_p, d_xw);
    cudaGetSymbolAddress((void**)&y_p,  d_y);

    const int warpGrid = div_up(N_NODES * 32, 256);
    const int edgeGrid = div_up(NEDGES, 256);
    const int gemmGrid = div_up(N_NODES, GM);
    const int aggGrid  = div_up(N_NODES, 8);     // 8 warps (nodes) per 256-thread block

    // CSR build
    init_k<<<div_up(N_NODES, 256), 256>>>();
    hist_k<<<edgeGrid, 256>>>(edge_index);
    scan_k<<<1, 1024>>>();
    selfloop_k<<<div_up(N_NODES, 256), 256>>>();
    scatter_k<<<edgeGrid, 256>>>(edge_index, edge_w);
    deg_k<<<warpGrid, 256>>>();
    csnorm_k<<<warpGrid, 256>>>();

    // features + input conv
    feat_k<<<N_NODES, 128>>>(poi_ids, cat_ids, feat3, poi_emb, cat_emb);
    gemm_tf32<<<gemmGrid, 256>>>(feat_p, Win, xw_p, N_NODES, FEAT_DIM);
    gcn_agg_v2<<<aggGrid, 256>>>(xw_p, b_in, x_p, 1);

    for (int l = 0; l < NLAYERS; l++) {
        // GCN unit half
        gemm_tf32<<<gemmGrid, 256>>>(x_p, gcn_W + l * CCH * CCH, xw_p, N_NODES, CCH);
        gcn_agg_v2<<<aggGrid, 256>>>(xw_p, gcn_b + l * CCH, y_p, 0);
        norm_reduce<<<592, 128>>>(y_p);
        norm_final<<<1, 128>>>(gn_alpha + l * CCH);
        norm_apply<<<div_up(N_NODES * CCH, 256), 256>>>(y_p, x_p, gn_gamma + l * CCH, gn_beta + l * CCH);

        // GAT unit half
        gemm_tf32<<<gemmGrid, 256>>>(x_p, gat_W + l * CCH * CCH, xw_p, N_NODES, CCH);
        alar_k<<<warpGrid, 256>>>(xw_p, gat_asrc + l * CCH, gat_adst + l * CCH);
        gat_agg_v2<<<aggGrid, 256>>>(xw_p, gat_b + l * CCH, y_p);
        norm_reduce<<<592, 128>>>(y_p);
        norm_final<<<1, 128>>>(gn_alpha + l * CCH);
        norm_apply<<<div_up(N_NODES * CCH, 256), 256>>>(y_p, x_p, gn_gamma + l * CCH, gn_beta + l * CCH);
    }

    // output conv + FC head
    gemv_out<<<warpGrid, 256>>>(x_p, Wout);
    scalar_agg<<<warpGrid, 256>>>(b_out);
    fc1_partial<<<592, 128>>>(fc_W1);
    fc1_final<<<1, 128>>>(fc_b1);
    fc2_k<<<div_up(POI_LEN_, 128), 128>>>(fc_W2, fc_b2, out);
}